// round 13
// baseline (speedup 1.0000x reference)
#include <cuda_runtime.h>

#define G        64
#define IMGSZ    512
#define CHSTRIDE (IMGSZ * IMGSZ)
#define NTHREADS 768

#define EDGE_SCALE (1.0f / 0.875f)   // all patch-edge wsums are 7/8

// S=4 tmp: [3][8][264]; col j at +2; pads {0,1,258,259}=0. Row = 66 float4s.
#define RP4 264
#define CH4 (8 * RP4)    // 2112
// S=2 tmp: [3][16][132]; col j at +1; pads {0,129}=0. Row = 66 float2s.
#define RP2 132
#define CH2 (16 * RP2)   // 2112

// ======================= S = 4 (img4 -> window 2) =======================
// Vertical-first; weights [1,3,5,7,7,5,3,1]/32. Chunk m = rows [4m-2,4m+2):
// s=[1,3,5,7]/32, t=[7,5,3,1]/32, out_y = s_y + t_{y+1}. Rows outside
// patch/image read 0; outputs y/i == 0/63 scaled by EDGE_SCALE.
// 768 threads: j = tid&255 (patch col), ch = tid>>8. One thread = one full
// 8-row slice column chain (9 chunks, 36 loads) -> minimal row re-reads.
__device__ void ds4_slice3(const float* __restrict__ imgb, float* __restrict__ ob,
                           int by, int bx, int y0, float* __restrict__ tmp) {
    const int tid = threadIdx.x;

    // zero pads: 24 rows (3ch x 8) x offsets {0,1,258,259}
    if (tid < 96) {
        int rs = tid >> 2, k = tid & 3;
        tmp[rs * RP4 + ((k < 2) ? k : 256 + k)] = 0.f;
    }

    // ---- phase 1: vertical ----
    {
        const int j  = tid & 255;
        const int ch = tid >> 8;           // 0..2
        const int gx = bx + j;
        float* trow = tmp + ch * CH4 + 2 + j;      // + (cm-1)*RP4
        if ((unsigned)gx >= (unsigned)IMGSZ) {
#pragma unroll
            for (int yy = 0; yy < 8; yy++) trow[yy * RP4] = 0.f;
        } else {
            const float* cimg = imgb + (size_t)ch * CHSTRIDE;
            const int rlo = 4 * y0 - 2;
            const bool allok = (rlo >= 0) && (rlo + 35 < 256) &&
                               (by + rlo >= 0) && (by + rlo + 35 < IMGSZ);
            float sp = 0.f;
            if (allok) {
                const float* p = cimg + (size_t)(by + rlo) * IMGSZ + gx;
#pragma unroll
                for (int cm = 0; cm <= 8; cm++) {
                    float v0 = __ldg(p + (4 * cm + 0) * IMGSZ);
                    float v1 = __ldg(p + (4 * cm + 1) * IMGSZ);
                    float v2 = __ldg(p + (4 * cm + 2) * IMGSZ);
                    float v3 = __ldg(p + (4 * cm + 3) * IMGSZ);
                    float s = fmaf(7.f/32, v3, fmaf(5.f/32, v2, fmaf(3.f/32, v1, (1.f/32)*v0)));
                    float t = fmaf(1.f/32, v3, fmaf(3.f/32, v2, fmaf(5.f/32, v1, (7.f/32)*v0)));
                    if (cm > 0) {
                        int y = y0 + cm - 1;
                        float r = sp + t;
                        if (y == 0 || y == 63) r *= EDGE_SCALE;
                        trow[(cm - 1) * RP4] = r;
                    }
                    sp = s;
                }
            } else {
#pragma unroll
                for (int cm = 0; cm <= 8; cm++) {
                    float v[4];
#pragma unroll
                    for (int k = 0; k < 4; k++) {
                        int r  = 4 * (y0 + cm) - 2 + k;
                        int gy = by + r;
                        bool ok = ((unsigned)r < 256u) & ((unsigned)gy < (unsigned)IMGSZ);
                        v[k] = ok ? __ldg(cimg + (size_t)(ok ? gy : 0) * IMGSZ + gx) : 0.f;
                    }
                    float s = fmaf(7.f/32, v[3], fmaf(5.f/32, v[2], fmaf(3.f/32, v[1], (1.f/32)*v[0])));
                    float t = fmaf(1.f/32, v[3], fmaf(3.f/32, v[2], fmaf(5.f/32, v[1], (7.f/32)*v[0])));
                    if (cm > 0) {
                        int y = y0 + cm - 1;
                        float r = sp + t;
                        if (y == 0 || y == 63) r *= EDGE_SCALE;
                        trow[(cm - 1) * RP4] = r;
                    }
                    sp = s;
                }
            }
        }
    }
    __syncthreads();

    // ---- phase 2: horizontal, aligned float4 chunks ----
    const float4* t4 = (const float4*)tmp;   // ch stride 528, row stride 66
#pragma unroll
    for (int u = 0; u < 2; u++) {
        int idx = tid + u * NTHREADS;        // 3*8*64 = 1536
        int ch = idx >> 9;
        int rem = idx & 511;
        int yy = rem >> 6, i = rem & 63;
        float4 a = t4[ch * 528 + yy * 66 + i];
        float4 b = t4[ch * 528 + yy * 66 + i + 1];
        float acc = (1.f/32)*a.x + (3.f/32)*a.y + (5.f/32)*a.z + (7.f/32)*a.w
                  + (7.f/32)*b.x + (5.f/32)*b.y + (3.f/32)*b.z + (1.f/32)*b.w;
        if (i == 0 || i == 63) acc *= EDGE_SCALE;
        ob[ch * (G * G) + (y0 + yy) * G + i] = acc;
    }
}

// ======================= S = 2 (img2 -> window 1) =======================
// Weights [1,3,3,1]/8; chunk m = rows {2m-1,2m}: s=[1,3]/8, t=[3,1]/8.
// 16 output rows per block. 768 threads: j = tid&127, g = tid>>7 (0..5):
// ch = g>>1, h = g&1 (8 rows each, 9 chunks = 18 loads).
__device__ void ds2_slice3(const float* __restrict__ imgb, float* __restrict__ ob,
                           int by, int bx, int y0, float* __restrict__ tmp) {
    const int tid = threadIdx.x;

    // zero pads: 48 rows x offsets {0,129}
    if (tid < 96) {
        int rs = tid >> 1, k = tid & 1;
        tmp[rs * RP2 + (k ? 129 : 0)] = 0.f;
    }

    // ---- phase 1: vertical ----
    {
        const int j  = tid & 127;
        const int g  = tid >> 7;           // 0..5
        const int ch = g >> 1;
        const int h  = g & 1;
        const int ylo = y0 + 8 * h;
        const int gx  = bx + j;
        float* trow = tmp + ch * CH2 + (8 * h) * RP2 + 1 + j;
        if ((unsigned)gx >= (unsigned)IMGSZ) {
#pragma unroll
            for (int yy = 0; yy < 8; yy++) trow[yy * RP2] = 0.f;
        } else {
            const float* cimg = imgb + (size_t)ch * CHSTRIDE;
            const int rlo = 2 * ylo - 1;
            const bool allok = (rlo >= 0) && (rlo + 17 < 128) &&
                               (by + rlo >= 0) && (by + rlo + 17 < IMGSZ);
            float sp = 0.f;
            if (allok) {
                const float* p = cimg + (size_t)(by + rlo) * IMGSZ + gx;
#pragma unroll
                for (int cm = 0; cm <= 8; cm++) {
                    float v0 = __ldg(p + (2 * cm + 0) * IMGSZ);
                    float v1 = __ldg(p + (2 * cm + 1) * IMGSZ);
                    float s = fmaf(3.f/8, v1, (1.f/8)*v0);
                    float t = fmaf(1.f/8, v1, (3.f/8)*v0);
                    if (cm > 0) {
                        int y = ylo + cm - 1;
                        float r = sp + t;
                        if (y == 0 || y == 63) r *= EDGE_SCALE;
                        trow[(cm - 1) * RP2] = r;
                    }
                    sp = s;
                }
            } else {
#pragma unroll
                for (int cm = 0; cm <= 8; cm++) {
                    float v[2];
#pragma unroll
                    for (int k = 0; k < 2; k++) {
                        int r  = 2 * (ylo + cm) - 1 + k;
                        int gy = by + r;
                        bool ok = ((unsigned)r < 128u) & ((unsigned)gy < (unsigned)IMGSZ);
                        v[k] = ok ? __ldg(cimg + (size_t)(ok ? gy : 0) * IMGSZ + gx) : 0.f;
                    }
                    float s = fmaf(3.f/8, v[1], (1.f/8)*v[0]);
                    float t = fmaf(1.f/8, v[1], (3.f/8)*v[0]);
                    if (cm > 0) {
                        int y = ylo + cm - 1;
                        float r = sp + t;
                        if (y == 0 || y == 63) r *= EDGE_SCALE;
                        trow[(cm - 1) * RP2] = r;
                    }
                    sp = s;
                }
            }
        }
    }
    __syncthreads();

    // ---- phase 2: horizontal, aligned float2 chunks ----
    const float2* t2 = (const float2*)tmp;   // ch stride 1056, row stride 66
#pragma unroll
    for (int u = 0; u < 4; u++) {
        int idx = tid + u * NTHREADS;        // 3*16*64 = 3072
        int ch = idx >> 10;
        int rem = idx & 1023;
        int yy = rem >> 6, i = rem & 63;
        float2 a = t2[ch * 1056 + yy * 66 + i];
        float2 b = t2[ch * 1056 + yy * 66 + i + 1];
        float acc = (1.f/8)*a.x + (3.f/8)*a.y + (3.f/8)*b.x + (1.f/8)*b.y;
        if (i == 0 || i == 63) acc *= EDGE_SCALE;
        ob[ch * (G * G) + (y0 + yy) * G + i] = acc;
    }
}

// Grid (832 blocks), heavy work first:
//   [0, 512)   : S=4, 8 slices x 8 rows per b (3 channels fused)
//   [512, 768) : S=2, 4 slices x 16 rows per b
//   [768, 832) : direct 64x64 zero-padded crop of img0, 3 channels
__global__ __launch_bounds__(NTHREADS, 2)
void glimpse_kernel(const float* __restrict__ img0,
                    const float* __restrict__ img2,
                    const float* __restrict__ img4,
                    const float* __restrict__ loc,
                    float* __restrict__ out) {
    extern __shared__ __align__(16) float tmp[];

    int blk = blockIdx.x;
    int sel, b, slice;
    if (blk < 512)      { sel = 0; b = blk >> 3;         slice = blk & 7; }
    else if (blk < 768) { sel = 1; b = (blk - 512) >> 2; slice = (blk - 512) & 3; }
    else                { sel = 2; b = blk - 768;        slice = 0; }

    // start index, matching jnp: trunc(0.5f * ((loc + 1.0f) * 511.0f))
    float lx = loc[2 * b + 0];
    float ly = loc[2 * b + 1];
    int sx = (int)(0.5f * ((lx + 1.0f) * 511.0f));
    int sy = (int)(0.5f * ((ly + 1.0f) * 511.0f));

    if (sel == 0) {
        const float* imgb = img4 + (size_t)b * 3 * CHSTRIDE;
        float* ob = out + (size_t)(b * 9 + 6) * (G * G);
        ds4_slice3(imgb, ob, sy - 128, sx - 128, slice * 8, tmp);
    } else if (sel == 1) {
        const float* imgb = img2 + (size_t)b * 3 * CHSTRIDE;
        float* ob = out + (size_t)(b * 9 + 3) * (G * G);
        ds2_slice3(imgb, ob, sy - 64, sx - 64, slice * 16, tmp);
    } else {
        const float* imgb = img0 + (size_t)b * 3 * CHSTRIDE;
        float* ob = out + (size_t)(b * 9 + 0) * (G * G);
        int by = sy - G / 2, bx = sx - G / 2;
        for (int idx = threadIdx.x; idx < G * G; idx += NTHREADS) {
            int y = idx >> 6, x = idx & 63;
            int gy = by + y, gx = bx + x;
            bool ok = (unsigned)gy < IMGSZ && (unsigned)gx < IMGSZ;
            const float* q = imgb + (size_t)(ok ? gy : 0) * IMGSZ + (ok ? gx : 0);
#pragma unroll
            for (int ch = 0; ch < 3; ch++)
                ob[ch * (G * G) + y * G + x] = ok ? __ldg(q + ch * CHSTRIDE) : 0.f;
        }
    }
}

extern "C" void kernel_launch(void* const* d_in, const int* in_sizes, int n_in,
                              void* d_out, int out_size) {
    const float* img0 = (const float*)d_in[0];
    const float* img2 = (const float*)d_in[1];
    const float* img4 = (const float*)d_in[2];
    const float* loc  = (const float*)d_in[3];
    float* out = (float*)d_out;

    const size_t smem = 3 * CH4 * sizeof(float);   // 25344 B (== 3*CH2*4)
    cudaFuncSetAttribute(glimpse_kernel,
                         cudaFuncAttributeMaxDynamicSharedMemorySize, (int)smem);
    glimpse_kernel<<<832, NTHREADS, smem>>>(img0, img2, img4, loc, out);
}

// round 14
// speedup vs baseline: 1.1775x; 1.1775x over previous
#include <cuda_runtime.h>

#define G        64
#define IMGSZ    512
#define CHSTRIDE (IMGSZ * IMGSZ)
#define NTHREADS 512

#define EDGE_SCALE (1.0f / 0.875f)   // all patch-edge wsums are 7/8

// S=4 tmp: [3][8][264]; col j at +2; pads {0,1,258,259}=0. Row = 66 float4s.
// S=2 tmp: [3][16][132]; col j at +1; pads {0,129}=0. Row = 66 float2s.

// ======================= S = 4 (img4 -> window 2) =======================
// Vertical-first separable filter, 3 channels fused (imm-offset variants of
// one address). Weights [1,3,5,7,7,5,3,1]/32; chunk m = rows [4m-2,4m+2):
// s_m=[1,3,5,7]/32, t_m=[7,5,3,1]/32, out_y = s_y + t_{y+1}. Rows outside
// patch/image are 0; outputs y/i == 0/63 get *EDGE_SCALE.
// 8 output rows per block; 512 threads = 256 cols x 2 row-halves; each
// thread runs 5 chunks x 3 channels (12 independent loads per chunk iter).
__device__ void ds4_slice3(const float* __restrict__ imgb, float* __restrict__ ob,
                           int by, int bx, int y0, float* __restrict__ tmp) {
    const int tid = threadIdx.x;

    // zero pads: 24 rows (3ch x 8, contiguous stride 264) x {0,1,258,259}
    if (tid < 96) {
        int rs = tid >> 2, k = tid & 3;
        tmp[rs * 264 + ((k < 2) ? k : 256 + k)] = 0.f;
    }

    // ---- phase 1: vertical; j = tid&255 (patch col), h = tid>>8 (4 rows) ----
    {
        const int j   = tid & 255;
        const int h   = tid >> 8;          // 0..1
        const int ylo = y0 + 4 * h;
        const int gx  = bx + j;
        float* tb = tmp + (4 * h) * 264 + 2 + j;   // + ch*2112 + cm*264 (imm)
        if ((unsigned)gx >= (unsigned)IMGSZ) {
#pragma unroll
            for (int ch = 0; ch < 3; ch++)
#pragma unroll
                for (int yy = 0; yy < 4; yy++) tb[ch * 2112 + yy * 264] = 0.f;
        } else {
            const int rlo = 4 * ylo - 2;
            const bool allok = (rlo >= 0) && (rlo + 19 < 256) &&
                               (by + rlo >= 0) && (by + rlo + 19 < IMGSZ);
            float sp[3] = {0.f, 0.f, 0.f};
            if (allok) {
                const float* p = imgb + (size_t)(by + rlo) * IMGSZ + gx;
#pragma unroll
                for (int cm = 0; cm <= 4; cm++) {
#pragma unroll
                    for (int ch = 0; ch < 3; ch++) {
                        const float* q = p + ch * CHSTRIDE + 4 * cm * IMGSZ;
                        float v0 = __ldg(q);
                        float v1 = __ldg(q + IMGSZ);
                        float v2 = __ldg(q + 2 * IMGSZ);
                        float v3 = __ldg(q + 3 * IMGSZ);
                        float s = fmaf(7.f/32, v3, fmaf(5.f/32, v2, fmaf(3.f/32, v1, (1.f/32)*v0)));
                        float t = fmaf(1.f/32, v3, fmaf(3.f/32, v2, fmaf(5.f/32, v1, (7.f/32)*v0)));
                        if (cm > 0) {
                            int y = ylo + cm - 1;
                            float r = sp[ch] + t;
                            if (y == 0 || y == 63) r *= EDGE_SCALE;
                            tb[ch * 2112 + (cm - 1) * 264] = r;
                        }
                        sp[ch] = s;
                    }
                }
            } else {
#pragma unroll
                for (int cm = 0; cm <= 4; cm++) {
                    float v[3][4];
#pragma unroll
                    for (int k = 0; k < 4; k++) {
                        int r  = 4 * (ylo + cm) - 2 + k;
                        int gy = by + r;
                        bool ok = (unsigned)r < 256u && (unsigned)gy < (unsigned)IMGSZ;
                        const float* q = imgb + (size_t)(ok ? gy : 0) * IMGSZ + gx;
#pragma unroll
                        for (int ch = 0; ch < 3; ch++)
                            v[ch][k] = ok ? __ldg(q + ch * CHSTRIDE) : 0.f;
                    }
#pragma unroll
                    for (int ch = 0; ch < 3; ch++) {
                        float s = fmaf(7.f/32, v[ch][3], fmaf(5.f/32, v[ch][2], fmaf(3.f/32, v[ch][1], (1.f/32)*v[ch][0])));
                        float t = fmaf(1.f/32, v[ch][3], fmaf(3.f/32, v[ch][2], fmaf(5.f/32, v[ch][1], (7.f/32)*v[ch][0])));
                        if (cm > 0) {
                            int y = ylo + cm - 1;
                            float r = sp[ch] + t;
                            if (y == 0 || y == 63) r *= EDGE_SCALE;
                            tb[ch * 2112 + (cm - 1) * 264] = r;
                        }
                        sp[ch] = s;
                    }
                }
            }
        }
    }
    __syncthreads();

    // ---- phase 2: horizontal, aligned float4 chunks, 3 ch per thread ----
    const float4* t4 = (const float4*)tmp;   // ch stride 528, row stride 66
    {
        int yy = tid >> 6, i = tid & 63;     // 8*64 == NTHREADS
        float* op = ob + (y0 + yy) * G + i;
#pragma unroll
        for (int ch = 0; ch < 3; ch++) {
            float4 a = t4[ch * 528 + yy * 66 + i];
            float4 b = t4[ch * 528 + yy * 66 + i + 1];
            float acc = (1.f/32)*a.x + (3.f/32)*a.y + (5.f/32)*a.z + (7.f/32)*a.w
                      + (7.f/32)*b.x + (5.f/32)*b.y + (3.f/32)*b.z + (1.f/32)*b.w;
            if (i == 0 || i == 63) acc *= EDGE_SCALE;
            op[ch * (G * G)] = acc;
        }
    }
}

// ======================= S = 2 (img2 -> window 1) =======================
// Weights [1,3,3,1]/8; chunk m = rows {2m-1,2m}: s=[1,3]/8, t=[3,1]/8.
// 16 output rows per block, 3 channels. tmp: [3][16][132]; col j at +1.
__device__ void ds2_slice3(const float* __restrict__ imgb, float* __restrict__ ob,
                           int by, int bx, int y0, float* __restrict__ tmp) {
    const int tid = threadIdx.x;

    // zero pads: 48 rows (contiguous, stride 132) x {0,129}
    if (tid < 96) {
        int rs = tid >> 1, k = tid & 1;
        tmp[rs * 132 + (k ? 129 : 0)] = 0.f;
    }

    // ---- phase 1: vertical; j = tid&127 (col), h = tid>>7 (4 rows each) ----
    {
        const int j   = tid & 127;
        const int h   = tid >> 7;            // 0..3
        const int ylo = y0 + 4 * h;
        const int gx  = bx + j;
        float* tb = tmp + (4 * h) * 132 + 1 + j;   // + ch*2112 + cm*132 (imm)
        if ((unsigned)gx >= (unsigned)IMGSZ) {
#pragma unroll
            for (int ch = 0; ch < 3; ch++)
#pragma unroll
                for (int yy = 0; yy < 4; yy++) tb[ch * 2112 + yy * 132] = 0.f;
        } else {
            const int rlo = 2 * ylo - 1;
            const bool allok = (rlo >= 0) && (rlo + 9 < 128) &&
                               (by + rlo >= 0) && (by + rlo + 9 < IMGSZ);
            float sp[3] = {0.f, 0.f, 0.f};
            if (allok) {
                const float* p = imgb + (size_t)(by + rlo) * IMGSZ + gx;
#pragma unroll
                for (int cm = 0; cm <= 4; cm++) {
#pragma unroll
                    for (int ch = 0; ch < 3; ch++) {
                        const float* q = p + ch * CHSTRIDE + 2 * cm * IMGSZ;
                        float v0 = __ldg(q);
                        float v1 = __ldg(q + IMGSZ);
                        float s = fmaf(3.f/8, v1, (1.f/8)*v0);
                        float t = fmaf(1.f/8, v1, (3.f/8)*v0);
                        if (cm > 0) {
                            int y = ylo + cm - 1;
                            float r = sp[ch] + t;
                            if (y == 0 || y == 63) r *= EDGE_SCALE;
                            tb[ch * 2112 + (cm - 1) * 132] = r;
                        }
                        sp[ch] = s;
                    }
                }
            } else {
#pragma unroll
                for (int cm = 0; cm <= 4; cm++) {
                    float v[3][2];
#pragma unroll
                    for (int k = 0; k < 2; k++) {
                        int r  = 2 * (ylo + cm) - 1 + k;
                        int gy = by + r;
                        bool ok = (unsigned)r < 128u && (unsigned)gy < (unsigned)IMGSZ;
                        const float* q = imgb + (size_t)(ok ? gy : 0) * IMGSZ + gx;
#pragma unroll
                        for (int ch = 0; ch < 3; ch++)
                            v[ch][k] = ok ? __ldg(q + ch * CHSTRIDE) : 0.f;
                    }
#pragma unroll
                    for (int ch = 0; ch < 3; ch++) {
                        float s = fmaf(3.f/8, v[ch][1], (1.f/8)*v[ch][0]);
                        float t = fmaf(1.f/8, v[ch][1], (3.f/8)*v[ch][0]);
                        if (cm > 0) {
                            int y = ylo + cm - 1;
                            float r = sp[ch] + t;
                            if (y == 0 || y == 63) r *= EDGE_SCALE;
                            tb[ch * 2112 + (cm - 1) * 132] = r;
                        }
                        sp[ch] = s;
                    }
                }
            }
        }
    }
    __syncthreads();

    // ---- phase 2: horizontal, aligned float2 chunks, 3 ch per thread ----
    const float2* t2 = (const float2*)tmp;   // ch stride 1056, row stride 66
#pragma unroll
    for (int u = 0; u < 2; u++) {
        int idx = tid + u * NTHREADS;        // 16*64 = 1024
        int yy = idx >> 6, i = idx & 63;
        float* op = ob + (y0 + yy) * G + i;
#pragma unroll
        for (int ch = 0; ch < 3; ch++) {
            float2 a = t2[ch * 1056 + yy * 66 + i];
            float2 b = t2[ch * 1056 + yy * 66 + i + 1];
            float acc = (1.f/8)*a.x + (3.f/8)*a.y + (3.f/8)*b.x + (1.f/8)*b.y;
            if (i == 0 || i == 63) acc *= EDGE_SCALE;
            op[ch * (G * G)] = acc;
        }
    }
}

// Grid (832 blocks), heavy work first:
//   [0, 512)   : S=4, 8 slices x 8 rows per b (3 channels fused)
//   [512, 768) : S=2, 4 slices x 16 rows per b
//   [768, 832) : direct 64x64 zero-padded crop of img0, 3 channels
__global__ __launch_bounds__(NTHREADS, 4)
void glimpse_kernel(const float* __restrict__ img0,
                    const float* __restrict__ img2,
                    const float* __restrict__ img4,
                    const float* __restrict__ loc,
                    float* __restrict__ out) {
    extern __shared__ __align__(16) float tmp[];

    int blk = blockIdx.x;
    int sel, b, slice;
    if (blk < 512)      { sel = 0; b = blk >> 3;         slice = blk & 7; }
    else if (blk < 768) { sel = 1; b = (blk - 512) >> 2; slice = (blk - 512) & 3; }
    else                { sel = 2; b = blk - 768;        slice = 0; }

    // start index, matching jnp: trunc(0.5f * ((loc + 1.0f) * 511.0f))
    float lx = loc[2 * b + 0];
    float ly = loc[2 * b + 1];
    int sx = (int)(0.5f * ((lx + 1.0f) * 511.0f));
    int sy = (int)(0.5f * ((ly + 1.0f) * 511.0f));

    if (sel == 0) {
        const float* imgb = img4 + (size_t)b * 3 * CHSTRIDE;
        float* ob = out + (size_t)(b * 9 + 6) * (G * G);
        ds4_slice3(imgb, ob, sy - 128, sx - 128, slice * 8, tmp);
    } else if (sel == 1) {
        const float* imgb = img2 + (size_t)b * 3 * CHSTRIDE;
        float* ob = out + (size_t)(b * 9 + 3) * (G * G);
        ds2_slice3(imgb, ob, sy - 64, sx - 64, slice * 16, tmp);
    } else {
        const float* imgb = img0 + (size_t)b * 3 * CHSTRIDE;
        float* ob = out + (size_t)(b * 9 + 0) * (G * G);
        int by = sy - G / 2, bx = sx - G / 2;
#pragma unroll
        for (int u = 0; u < 8; u++) {
            int idx = threadIdx.x + u * NTHREADS;   // 4096 positions
            int y = idx >> 6, x = idx & 63;
            int gy = by + y, gx = bx + x;
            bool ok = (unsigned)gy < IMGSZ && (unsigned)gx < IMGSZ;
            const float* q = imgb + (size_t)(ok ? gy : 0) * IMGSZ + (ok ? gx : 0);
#pragma unroll
            for (int ch = 0; ch < 3; ch++)
                ob[ch * (G * G) + y * G + x] = ok ? __ldg(q + ch * CHSTRIDE) : 0.f;
        }
    }
}

extern "C" void kernel_launch(void* const* d_in, const int* in_sizes, int n_in,
                              void* d_out, int out_size) {
    const float* img0 = (const float*)d_in[0];
    const float* img2 = (const float*)d_in[1];
    const float* img4 = (const float*)d_in[2];
    const float* loc  = (const float*)d_in[3];
    float* out = (float*)d_out;

    const size_t smem = 25344;   // 3 * 8 * 264 * 4 == 3 * 16 * 132 * 4
    cudaFuncSetAttribute(glimpse_kernel,
                         cudaFuncAttributeMaxDynamicSharedMemorySize, (int)smem);
    glimpse_kernel<<<832, NTHREADS, smem>>>(img0, img2, img4, loc, out);
}